// round 7
// baseline (speedup 1.0000x reference)
#include <cuda_runtime.h>
#include <math.h>

#define VOCAB 433
#define DMODEL 120
#define BATCH 4096
#define SEQL 16
#define H4 480
#define MTOK (BATCH*SEQL)   // 65536

// Scratch (static __device__ arrays: allocation-free per harness rules)
__device__ float g_xg[(size_t)MTOK * H4];     // 125.8 MB
__device__ float g_h [(size_t)MTOK * DMODEL]; // 31.5 MB
__device__ float g_ln[(size_t)MTOK * DMODEL]; // 31.5 MB

// Accurate activations (ex2-based; 2^-22.5 max err even under fast-math).
#define LOG2E 1.4426950408889634f
__device__ __forceinline__ float sig_acc(float x) {
    return 1.0f / (1.0f + exp2f(-x * LOG2E));
}
__device__ __forceinline__ float tanh_acc(float x) {
    float e = exp2f(x * (2.0f * LOG2E));        // exp(2x)
    return 1.0f - 2.0f / (e + 1.0f);            // +-1 saturation via inf/0
}

// ---------------------------------------------------------------------------
// GEMM: C[M,N] = A[M,120] * W[N,120]^T (+ b1 + b2), exact fp32.
// A row m optionally gathered: A_row = Emb[idx[m]].
// Block tile 128x64, 128 threads, each thread 8x8. K=120 in 3 tiles of 40.
// ---------------------------------------------------------------------------
template<bool GATHER>
__global__ __launch_bounds__(128)
void gemm_k(const float* __restrict__ A,
            const int*   __restrict__ idx,
            const float* __restrict__ Emb,
            const float* __restrict__ W,
            const float* __restrict__ b1,
            const float* __restrict__ b2,
            float* __restrict__ C, int N)
{
    __shared__ float As[40][128];   // [k][m]
    __shared__ float Ws[40][64];    // [k][n]

    const int tid = threadIdx.x;
    const int m0  = blockIdx.x * 128;
    const int n0  = blockIdx.y * 64;
    const int tx  = tid & 15;       // m-group (16 groups of 8 rows)
    const int ty  = tid >> 4;       // n-group (8 groups of 8 cols)

    const float* arow;
    if (GATHER) arow = Emb + (size_t)idx[m0 + tid] * DMODEL;
    else        arow = A   + (size_t)(m0 + tid) * DMODEL;

    float acc[8][8];
#pragma unroll
    for (int i = 0; i < 8; i++)
#pragma unroll
        for (int j = 0; j < 8; j++) acc[i][j] = 0.0f;

#pragma unroll 1
    for (int kt = 0; kt < 3; kt++) {
        const int k0 = kt * 40;
        // Load A tile: thread tid owns row tid, 40 floats along k.
#pragma unroll
        for (int i = 0; i < 10; i++) {
            float4 v = *(const float4*)(arow + k0 + i * 4);
            As[i*4+0][tid] = v.x;
            As[i*4+1][tid] = v.y;
            As[i*4+2][tid] = v.z;
            As[i*4+3][tid] = v.w;
        }
        // Load W tile (zero-fill past N)
#pragma unroll
        for (int i = 0; i < 5; i++) {
            int flat = i * 128 + tid;          // 0..639
            int n  = flat & 63;
            int k4 = flat >> 6;                // 0..9
            float4 v = make_float4(0.f, 0.f, 0.f, 0.f);
            if (n0 + n < N)
                v = *(const float4*)(W + (size_t)(n0 + n) * DMODEL + k0 + k4 * 4);
            Ws[k4*4+0][n] = v.x;
            Ws[k4*4+1][n] = v.y;
            Ws[k4*4+2][n] = v.z;
            Ws[k4*4+3][n] = v.w;
        }
        __syncthreads();
#pragma unroll 4
        for (int k = 0; k < 40; k++) {
            float4 a0 = *(const float4*)&As[k][tx * 8];
            float4 a1 = *(const float4*)&As[k][tx * 8 + 4];
            float4 w0 = *(const float4*)&Ws[k][ty * 8];
            float4 w1 = *(const float4*)&Ws[k][ty * 8 + 4];
            float a[8] = {a0.x, a0.y, a0.z, a0.w, a1.x, a1.y, a1.z, a1.w};
            float w[8] = {w0.x, w0.y, w0.z, w0.w, w1.x, w1.y, w1.z, w1.w};
#pragma unroll
            for (int i = 0; i < 8; i++)
#pragma unroll
                for (int j = 0; j < 8; j++)
                    acc[i][j] += a[i] * w[j];
        }
        __syncthreads();
    }

    // Epilogue
    float bias[8];
#pragma unroll
    for (int j = 0; j < 8; j++) {
        int n = n0 + ty * 8 + j;
        float b = 0.0f;
        if (n < N) {
            if (b1) b += b1[n];
            if (b2) b += b2[n];
        }
        bias[j] = b;
    }
#pragma unroll
    for (int i = 0; i < 8; i++) {
        const int m = m0 + tx * 8 + i;
        float* crow = C + (size_t)m * N;
#pragma unroll
        for (int j = 0; j < 8; j++) {
            int n = n0 + ty * 8 + j;
            if (n < N) crow[n] = acc[i][j] + bias[j];
        }
    }
}

// ---------------------------------------------------------------------------
// LSTM layer: one block handles 16 batch rows for all 16 timesteps.
// 256 threads. Gate phase: threads 0..239 each own 2 gate rows (g, g+240),
// accumulate over all 16 rows with Whh float4 loads (L1-resident) and
// h broadcast from smem. Update phase: c in registers, i/f/g/o from smem.
// ---------------------------------------------------------------------------
__global__ __launch_bounds__(256)
void lstm_k(const float* __restrict__ xg,
            const float* __restrict__ Whh,
            float* __restrict__ hout)
{
    __shared__ float h_s[16][DMODEL];
    __shared__ float gates_s[16][H4];

    const int tid = threadIdx.x;
    const int b0  = blockIdx.x * 16;

    // Update-phase cell mapping (constant across timesteps): cell = tid + 256*i
    int rr[8], dd[8];
    float c[8];
#pragma unroll
    for (int i = 0; i < 8; i++) {
        int cell = tid + 256 * i;
        rr[i] = cell / DMODEL;
        dd[i] = cell % DMODEL;
        c[i]  = 0.0f;
    }

#pragma unroll 1
    for (int t = 0; t < SEQL; t++) {
        if (tid < 240) {
            const int g0 = tid;
            const int g1 = tid + 240;
            float acc0[16], acc1[16];
#pragma unroll
            for (int r = 0; r < 16; r++) {
                size_t base = ((size_t)(b0 + r) * SEQL + t) * H4;
                acc0[r] = xg[base + g0];
                acc1[r] = xg[base + g1];
            }
            if (t > 0) {
                const float* w0p = Whh + (size_t)g0 * DMODEL;
                const float* w1p = Whh + (size_t)g1 * DMODEL;
#pragma unroll 2
                for (int k = 0; k < DMODEL; k += 4) {
                    float4 w0 = *(const float4*)(w0p + k);
                    float4 w1 = *(const float4*)(w1p + k);
#pragma unroll
                    for (int r = 0; r < 16; r++) {
                        float4 hv = *(const float4*)&h_s[r][k];
                        acc0[r] += hv.x*w0.x + hv.y*w0.y + hv.z*w0.z + hv.w*w0.w;
                        acc1[r] += hv.x*w1.x + hv.y*w1.y + hv.z*w1.z + hv.w*w1.w;
                    }
                }
            }
#pragma unroll
            for (int r = 0; r < 16; r++) {
                gates_s[r][g0] = acc0[r];
                gates_s[r][g1] = acc1[r];
            }
        }
        __syncthreads();
        // Pointwise LSTM cell update (gate order i, f, g, o)
#pragma unroll
        for (int i = 0; i < 8; i++) {
            int cell = tid + 256 * i;
            if (cell < 16 * DMODEL) {
                const int r = rr[i], d = dd[i];
                float gi = gates_s[r][d];
                float gf = gates_s[r][DMODEL + d];
                float gg = gates_s[r][2 * DMODEL + d];
                float go = gates_s[r][3 * DMODEL + d];
                float cn = sig_acc(gf) * c[i] + sig_acc(gi) * tanh_acc(gg);
                c[i] = cn;
                float h = sig_acc(go) * tanh_acc(cn);
                h_s[r][d] = h;
                hout[((size_t)(b0 + r) * SEQL + t) * DMODEL + d] = h;
            }
        }
        __syncthreads();
    }
}

// ---------------------------------------------------------------------------
// LayerNorm over D=120: one warp per row (exact fp32).
// ---------------------------------------------------------------------------
__global__ __launch_bounds__(256)
void ln_k(const float* __restrict__ in,
          const float* __restrict__ gamma,
          const float* __restrict__ beta,
          float* __restrict__ out)
{
    const int row  = blockIdx.x * 8 + (threadIdx.x >> 5);
    const int lane = threadIdx.x & 31;
    const float* rp = in + (size_t)row * DMODEL;

    float v[4];
    float s = 0.0f, s2 = 0.0f;
#pragma unroll
    for (int i = 0; i < 4; i++) {
        int d = lane + 32 * i;
        v[i] = (d < DMODEL) ? rp[d] : 0.0f;
        s  += v[i];
        s2 += v[i] * v[i];
    }
#pragma unroll
    for (int off = 16; off > 0; off >>= 1) {
        s  += __shfl_xor_sync(0xffffffffu, s,  off);
        s2 += __shfl_xor_sync(0xffffffffu, s2, off);
    }
    const float mu   = s  * (1.0f / DMODEL);
    const float var  = s2 * (1.0f / DMODEL) - mu * mu;
    const float rstd = rsqrtf(var + 1e-5f);

    float* op = out + (size_t)row * DMODEL;
#pragma unroll
    for (int i = 0; i < 4; i++) {
        int d = lane + 32 * i;
        if (d < DMODEL)
            op[d] = (v[i] - mu) * rstd * gamma[d] + beta[d];
    }
}

// ---------------------------------------------------------------------------
extern "C" void kernel_launch(void* const* d_in, const int* in_sizes, int n_in,
                              void* d_out, int out_size)
{
    const int*   x     = (const int*)  d_in[0];
    const float* embed = (const float*)d_in[1];
    const float* Wih0  = (const float*)d_in[2];
    const float* Whh0  = (const float*)d_in[3];
    const float* bih0  = (const float*)d_in[4];
    const float* bhh0  = (const float*)d_in[5];
    const float* Wih1  = (const float*)d_in[6];
    const float* Whh1  = (const float*)d_in[7];
    const float* bih1  = (const float*)d_in[8];
    const float* bhh1  = (const float*)d_in[9];
    const float* gamma = (const float*)d_in[10];
    const float* beta  = (const float*)d_in[11];
    float* out = (float*)d_out;

    float *xg, *h, *ln;
    cudaGetSymbolAddress((void**)&xg, g_xg);
    cudaGetSymbolAddress((void**)&h,  g_h);
    cudaGetSymbolAddress((void**)&ln, g_ln);

    // THE R1-R4 BUG: H4/64 = 480/64 floored to 7, leaving xg columns 448..479
    // (last 32 o-gate dims) never written. Ceil-divide everywhere now.
    dim3 g480(MTOK / 128, (H4 + 63) / 64);     // (512, 8)
    dim3 g433(MTOK / 128, (VOCAB + 63) / 64);  // (512, 7)

    // Layer 0: xg0 = embed[x] @ Wih0^T + bih0 + bhh0 (gather fused)
    gemm_k<true ><<<g480, 128>>>(nullptr, x, embed, Wih0, bih0, bhh0, xg, H4);
    // LSTM layer 0 recurrence
    lstm_k<<<BATCH / 16, 256>>>(xg, Whh0, h);
    // Layer 1: xg1 = h0 @ Wih1^T + bih1 + bhh1
    gemm_k<false><<<g480, 128>>>(h, nullptr, nullptr, Wih1, bih1, bhh1, xg, H4);
    // LSTM layer 1 recurrence (reuse h buffer)
    lstm_k<<<BATCH / 16, 256>>>(xg, Whh1, h);
    // LayerNorm
    ln_k<<<MTOK / 8, 256>>>(h, gamma, beta, ln);
    // Tied-embedding head: logits = ln @ embed^T
    gemm_k<false><<<g433, 128>>>(ln, nullptr, nullptr, embed, nullptr, nullptr,
                                 out, VOCAB);
}

// round 8
// speedup vs baseline: 1.5017x; 1.5017x over previous
#include <cuda_runtime.h>
#include <math.h>

#define VOCAB 433
#define DMODEL 120
#define BATCH 4096
#define SEQL 16
#define H4 480
#define MTOK (BATCH*SEQL)   // 65536

// Scratch (static __device__ arrays: allocation-free per harness rules)
__device__ float g_xg[(size_t)MTOK * H4];     // 125.8 MB
__device__ float g_h [(size_t)MTOK * DMODEL]; // 31.5 MB
__device__ float g_ln[(size_t)MTOK * DMODEL]; // 31.5 MB

// Accurate activations (ex2-based; 2^-22.5 max err even under fast-math).
#define LOG2E 1.4426950408889634f
__device__ __forceinline__ float sig_acc(float x) {
    return 1.0f / (1.0f + exp2f(-x * LOG2E));
}
__device__ __forceinline__ float tanh_acc(float x) {
    float e = exp2f(x * (2.0f * LOG2E));        // exp(2x)
    return 1.0f - 2.0f / (e + 1.0f);            // +-1 saturation via inf/0
}

// Round fp32 -> tf32 (RNE). Validated in R4: tf32 operands add only ~1e-4
// rel_err vs exact fp32 on this network -- 10x under the 1e-3 threshold.
__device__ __forceinline__ float tf32r(float x) {
    float r;
    asm("cvt.rna.tf32.f32 %0, %1;" : "=f"(r) : "f"(x));
    return r;
}

// m16n8k8 tf32 tensor-core mma, fp32 accumulate.
__device__ __forceinline__ void mma_tf32(float* d, const unsigned* a,
                                         const unsigned* b) {
    asm volatile(
        "mma.sync.aligned.m16n8k8.row.col.f32.tf32.tf32.f32 "
        "{%0,%1,%2,%3}, {%4,%5,%6,%7}, {%8,%9}, {%0,%1,%2,%3};\n"
        : "+f"(d[0]), "+f"(d[1]), "+f"(d[2]), "+f"(d[3])
        : "r"(a[0]), "r"(a[1]), "r"(a[2]), "r"(a[3]), "r"(b[0]), "r"(b[1]));
}

// ---------------------------------------------------------------------------
// Tensor-core GEMM: C[M,N] = A[M,120] @ W[N,120]^T (+ b1 + b2), tf32 mma,
// fp32 accumulate. A row m optionally gathered: A_row = Emb[idx[m]].
// Block tile 128x128, 256 threads = 8 warps (4 m-warps x 2 n-warps, each
// warp m32 x n64). K=120 staged in 3 smem chunks of 40 (5 k8 mma steps).
// smem [m][k] stride 44: frag-load bank pattern (12g+tg)%32 conflict-free.
// ---------------------------------------------------------------------------
template<bool GATHER>
__global__ __launch_bounds__(256, 2)
void gemm_tc(const float* __restrict__ A,
             const int*   __restrict__ idx,
             const float* __restrict__ Emb,
             const float* __restrict__ W,
             const float* __restrict__ b1,
             const float* __restrict__ b2,
             float* __restrict__ C, int N)
{
    __shared__ float As[128][44];   // 22.5 KB
    __shared__ float Ws[128][44];   // 22.5 KB

    const int tid  = threadIdx.x;
    const int wid  = tid >> 5;
    const int lane = tid & 31;
    const int g    = lane >> 2;     // group id 0..7
    const int tg   = lane & 3;      // thread-in-group 0..3
    const int m0   = blockIdx.x * 128;
    const int n0   = blockIdx.y * 128;
    const int wm   = wid >> 1;      // m-warp 0..3 (m32 each)
    const int wn   = wid & 1;       // n-warp 0..1 (n64 each)

    float acc[2][8][4];
#pragma unroll
    for (int mf = 0; mf < 2; mf++)
#pragma unroll
        for (int nf = 0; nf < 8; nf++)
#pragma unroll
            for (int i = 0; i < 4; i++) acc[mf][nf][i] = 0.0f;

#pragma unroll 1
    for (int kt = 0; kt < 3; kt++) {
        const int k0g = kt * 40;
        // Load A chunk: 128 rows x 40 floats = 1280 float4, 5 per thread.
#pragma unroll
        for (int i = 0; i < 5; i++) {
            int flat = tid + i * 256;       // 0..1279
            int row = flat / 10, c4 = flat % 10;
            const float* src;
            if (GATHER)
                src = Emb + (size_t)idx[m0 + row] * DMODEL + k0g + c4 * 4;
            else
                src = A + (size_t)(m0 + row) * DMODEL + k0g + c4 * 4;
            float4 v = *(const float4*)src;
            As[row][c4*4+0] = tf32r(v.x);
            As[row][c4*4+1] = tf32r(v.y);
            As[row][c4*4+2] = tf32r(v.z);
            As[row][c4*4+3] = tf32r(v.w);
        }
        // Load W chunk (zero-fill rows past N).
#pragma unroll
        for (int i = 0; i < 5; i++) {
            int flat = tid + i * 256;
            int row = flat / 10, c4 = flat % 10;
            float4 v = make_float4(0.f, 0.f, 0.f, 0.f);
            if (n0 + row < N)
                v = *(const float4*)(W + (size_t)(n0 + row) * DMODEL + k0g + c4 * 4);
            Ws[row][c4*4+0] = tf32r(v.x);
            Ws[row][c4*4+1] = tf32r(v.y);
            Ws[row][c4*4+2] = tf32r(v.z);
            Ws[row][c4*4+3] = tf32r(v.w);
        }
        __syncthreads();

#pragma unroll
        for (int kk = 0; kk < 5; kk++) {
            const int k0 = kk * 8;
            unsigned a[2][4];
#pragma unroll
            for (int mf = 0; mf < 2; mf++) {
                int m = wm * 32 + mf * 16 + g;
                a[mf][0] = __float_as_uint(As[m    ][k0 + tg    ]);
                a[mf][1] = __float_as_uint(As[m + 8][k0 + tg    ]);
                a[mf][2] = __float_as_uint(As[m    ][k0 + tg + 4]);
                a[mf][3] = __float_as_uint(As[m + 8][k0 + tg + 4]);
            }
#pragma unroll
            for (int nf = 0; nf < 8; nf++) {
                unsigned b[2];
                int n = wn * 64 + nf * 8 + g;
                b[0] = __float_as_uint(Ws[n][k0 + tg    ]);
                b[1] = __float_as_uint(Ws[n][k0 + tg + 4]);
                mma_tf32(acc[0][nf], a[0], b);
                mma_tf32(acc[1][nf], a[1], b);
            }
        }
        __syncthreads();
    }

    // Epilogue: bias + guarded scalar stores.
#pragma unroll
    for (int mf = 0; mf < 2; mf++) {
        const int m = m0 + wm * 32 + mf * 16 + g;
#pragma unroll
        for (int nf = 0; nf < 8; nf++) {
            const int n = n0 + wn * 64 + nf * 8 + 2 * tg;
            float bs0 = 0.0f, bs1 = 0.0f;
            if (n < N)     { if (b1) bs0 += b1[n];     if (b2) bs0 += b2[n]; }
            if (n + 1 < N) { if (b1) bs1 += b1[n + 1]; if (b2) bs1 += b2[n + 1]; }
            float* r0 = C + (size_t)m * N;
            float* r1 = C + (size_t)(m + 8) * N;
            if (n < N) {
                r0[n] = acc[mf][nf][0] + bs0;
                r1[n] = acc[mf][nf][2] + bs0;
            }
            if (n + 1 < N) {
                r0[n + 1] = acc[mf][nf][1] + bs1;
                r1[n + 1] = acc[mf][nf][3] + bs1;
            }
        }
    }
}

// ---------------------------------------------------------------------------
// LSTM layer: one block handles 16 batch rows for all 16 timesteps.
// 256 threads. Gate phase: threads 0..239 each own 2 gate rows (g, g+240),
// accumulate over all 16 rows with Whh float4 loads (L1-resident) and
// h broadcast from smem. Update phase: c in registers, i/f/g/o from smem.
// (exact fp32 -- unchanged, known-good)
// ---------------------------------------------------------------------------
__global__ __launch_bounds__(256)
void lstm_k(const float* __restrict__ xg,
            const float* __restrict__ Whh,
            float* __restrict__ hout)
{
    __shared__ float h_s[16][DMODEL];
    __shared__ float gates_s[16][H4];

    const int tid = threadIdx.x;
    const int b0  = blockIdx.x * 16;

    int rr[8], dd[8];
    float c[8];
#pragma unroll
    for (int i = 0; i < 8; i++) {
        int cell = tid + 256 * i;
        rr[i] = cell / DMODEL;
        dd[i] = cell % DMODEL;
        c[i]  = 0.0f;
    }

#pragma unroll 1
    for (int t = 0; t < SEQL; t++) {
        if (tid < 240) {
            const int g0 = tid;
            const int g1 = tid + 240;
            float acc0[16], acc1[16];
#pragma unroll
            for (int r = 0; r < 16; r++) {
                size_t base = ((size_t)(b0 + r) * SEQL + t) * H4;
                acc0[r] = xg[base + g0];
                acc1[r] = xg[base + g1];
            }
            if (t > 0) {
                const float* w0p = Whh + (size_t)g0 * DMODEL;
                const float* w1p = Whh + (size_t)g1 * DMODEL;
#pragma unroll 2
                for (int k = 0; k < DMODEL; k += 4) {
                    float4 w0 = *(const float4*)(w0p + k);
                    float4 w1 = *(const float4*)(w1p + k);
#pragma unroll
                    for (int r = 0; r < 16; r++) {
                        float4 hv = *(const float4*)&h_s[r][k];
                        acc0[r] += hv.x*w0.x + hv.y*w0.y + hv.z*w0.z + hv.w*w0.w;
                        acc1[r] += hv.x*w1.x + hv.y*w1.y + hv.z*w1.z + hv.w*w1.w;
                    }
                }
            }
#pragma unroll
            for (int r = 0; r < 16; r++) {
                gates_s[r][g0] = acc0[r];
                gates_s[r][g1] = acc1[r];
            }
        }
        __syncthreads();
        // Pointwise LSTM cell update (gate order i, f, g, o)
#pragma unroll
        for (int i = 0; i < 8; i++) {
            int cell = tid + 256 * i;
            if (cell < 16 * DMODEL) {
                const int r = rr[i], d = dd[i];
                float gi = gates_s[r][d];
                float gf = gates_s[r][DMODEL + d];
                float gg = gates_s[r][2 * DMODEL + d];
                float go = gates_s[r][3 * DMODEL + d];
                float cn = sig_acc(gf) * c[i] + sig_acc(gi) * tanh_acc(gg);
                c[i] = cn;
                float h = sig_acc(go) * tanh_acc(cn);
                h_s[r][d] = h;
                hout[((size_t)(b0 + r) * SEQL + t) * DMODEL + d] = h;
            }
        }
        __syncthreads();
    }
}

// ---------------------------------------------------------------------------
// LayerNorm over D=120: one warp per row (exact fp32).
// ---------------------------------------------------------------------------
__global__ __launch_bounds__(256)
void ln_k(const float* __restrict__ in,
          const float* __restrict__ gamma,
          const float* __restrict__ beta,
          float* __restrict__ out)
{
    const int row  = blockIdx.x * 8 + (threadIdx.x >> 5);
    const int lane = threadIdx.x & 31;
    const float* rp = in + (size_t)row * DMODEL;

    float v[4];
    float s = 0.0f, s2 = 0.0f;
#pragma unroll
    for (int i = 0; i < 4; i++) {
        int d = lane + 32 * i;
        v[i] = (d < DMODEL) ? rp[d] : 0.0f;
        s  += v[i];
        s2 += v[i] * v[i];
    }
#pragma unroll
    for (int off = 16; off > 0; off >>= 1) {
        s  += __shfl_xor_sync(0xffffffffu, s,  off);
        s2 += __shfl_xor_sync(0xffffffffu, s2, off);
    }
    const float mu   = s  * (1.0f / DMODEL);
    const float var  = s2 * (1.0f / DMODEL) - mu * mu;
    const float rstd = rsqrtf(var + 1e-5f);

    float* op = out + (size_t)row * DMODEL;
#pragma unroll
    for (int i = 0; i < 4; i++) {
        int d = lane + 32 * i;
        if (d < DMODEL)
            op[d] = (v[i] - mu) * rstd * gamma[d] + beta[d];
    }
}

// ---------------------------------------------------------------------------
extern "C" void kernel_launch(void* const* d_in, const int* in_sizes, int n_in,
                              void* d_out, int out_size)
{
    const int*   x     = (const int*)  d_in[0];
    const float* embed = (const float*)d_in[1];
    const float* Wih0  = (const float*)d_in[2];
    const float* Whh0  = (const float*)d_in[3];
    const float* bih0  = (const float*)d_in[4];
    const float* bhh0  = (const float*)d_in[5];
    const float* Wih1  = (const float*)d_in[6];
    const float* Whh1  = (const float*)d_in[7];
    const float* bih1  = (const float*)d_in[8];
    const float* bhh1  = (const float*)d_in[9];
    const float* gamma = (const float*)d_in[10];
    const float* beta  = (const float*)d_in[11];
    float* out = (float*)d_out;

    float *xg, *h, *ln;
    cudaGetSymbolAddress((void**)&xg, g_xg);
    cudaGetSymbolAddress((void**)&h,  g_h);
    cudaGetSymbolAddress((void**)&ln, g_ln);

    dim3 g480(MTOK / 128, (H4 + 127) / 128);     // (512, 4)
    dim3 g433(MTOK / 128, (VOCAB + 127) / 128);  // (512, 4)

    // Layer 0: xg0 = embed[x] @ Wih0^T + bih0 + bhh0 (gather fused, tf32 TC)
    gemm_tc<true ><<<g480, 256>>>(nullptr, x, embed, Wih0, bih0, bhh0, xg, H4);
    // LSTM layer 0 recurrence (exact fp32)
    lstm_k<<<BATCH / 16, 256>>>(xg, Whh0, h);
    // Layer 1: xg1 = h0 @ Wih1^T + bih1 + bhh1 (tf32 TC)
    gemm_tc<false><<<g480, 256>>>(h, nullptr, nullptr, Wih1, bih1, bhh1, xg, H4);
    // LSTM layer 1 recurrence (reuse h buffer)
    lstm_k<<<BATCH / 16, 256>>>(xg, Whh1, h);
    // LayerNorm
    ln_k<<<MTOK / 8, 256>>>(h, gamma, beta, ln);
    // Tied-embedding head: logits = ln @ embed^T (tf32 TC)
    gemm_tc<false><<<g433, 256>>>(ln, nullptr, nullptr, embed, nullptr, nullptr,
                                  out, VOCAB);
}

// round 9
// speedup vs baseline: 1.8390x; 1.2246x over previous
#include <cuda_runtime.h>
#include <math.h>

#define VOCAB 433
#define DMODEL 120
#define BATCH 4096
#define SEQL 16
#define H4 480
#define MTOK (BATCH*SEQL)   // 65536

#define NT_TILES 60          // 480/8 n-tiles
#define KT_TILES 15          // 120/8 k-tiles
#define WPK_ELEMS (NT_TILES*KT_TILES*64)   // 57600 floats per matrix

// Scratch (static __device__ arrays: allocation-free per harness rules)
__device__ float g_xg[(size_t)MTOK * H4];     // 125.8 MB
__device__ float g_h [(size_t)MTOK * DMODEL]; // 31.5 MB
__device__ float g_ln[(size_t)MTOK * DMODEL]; // 31.5 MB
__device__ float g_wpk[2][WPK_ELEMS];         // fragment-packed tf32 Whh0/Whh1

// Accurate activations (ex2-based; 2^-22.5 max err even under fast-math).
#define LOG2E 1.4426950408889634f
__device__ __forceinline__ float sig_acc(float x) {
    return 1.0f / (1.0f + exp2f(-x * LOG2E));
}
__device__ __forceinline__ float tanh_acc(float x) {
    float e = exp2f(x * (2.0f * LOG2E));        // exp(2x)
    return 1.0f - 2.0f / (e + 1.0f);            // +-1 saturation via inf/0
}

// Round fp32 -> tf32 (RNE). R4-validated: tf32 operands everywhere (incl. the
// recurrence) add only ~1e-4 rel_err on this network.
__device__ __forceinline__ float tf32r(float x) {
    float r;
    asm("cvt.rna.tf32.f32 %0, %1;" : "=f"(r) : "f"(x));
    return r;
}

// m16n8k8 tf32 tensor-core mma, fp32 accumulate.
__device__ __forceinline__ void mma_tf32(float* d, const unsigned* a,
                                         const unsigned* b) {
    asm volatile(
        "mma.sync.aligned.m16n8k8.row.col.f32.tf32.tf32.f32 "
        "{%0,%1,%2,%3}, {%4,%5,%6,%7}, {%8,%9}, {%0,%1,%2,%3};\n"
        : "+f"(d[0]), "+f"(d[1]), "+f"(d[2]), "+f"(d[3])
        : "r"(a[0]), "r"(a[1]), "r"(a[2]), "r"(a[3]), "r"(b[0]), "r"(b[1]));
}

// ---------------------------------------------------------------------------
// Pack Whh[480,120] into per-(n8,k8)-tile B-fragment layout, tf32-rounded:
// Wpk[(nt*15+kt)*64 + lane*2 + j] = tf32(Whh[nt*8+g][kt*8+tg+4*j]),
// g=lane>>2, tg=lane&3. One coalesced LDG.64 per warp per tile at use site.
// ---------------------------------------------------------------------------
__global__ void pack_whh(const float* __restrict__ Whh, float* __restrict__ Wpk)
{
    int idx = blockIdx.x * 256 + threadIdx.x;     // 0..28799
    if (idx >= NT_TILES * KT_TILES * 32) return;
    int lane = idx & 31, tile = idx >> 5;
    int kt = tile % KT_TILES, nt = tile / KT_TILES;
    int g = lane >> 2, tg = lane & 3;
    int n = nt * 8 + g;
    int k = kt * 8 + tg;
    Wpk[tile * 64 + lane * 2 + 0] = tf32r(Whh[n * DMODEL + k]);
    Wpk[tile * 64 + lane * 2 + 1] = tf32r(Whh[n * DMODEL + k + 4]);
}

// ---------------------------------------------------------------------------
// Tensor-core LSTM layer: block = 16 batch rows x 16 timesteps, 256 thr/8 wrp.
// Per step: gates[16,480] = h[16,120] @ Whh^T via m16n8k8 tf32 mma
// (one m16 tile; 60 n8-tiles split 8/8/8/8/7/7/7/7 across warps; B-frags
// streamed from the packed L1-resident buffer). Pointwise phase adds xg
// (exact fp32) and applies the cell update; h_s stores tf32-rounded h.
// ---------------------------------------------------------------------------
#define NPAD 124
#define GPAD 488
__global__ __launch_bounds__(256)
void lstm_tc(const float* __restrict__ xg,
             const float* __restrict__ Wpk,
             float* __restrict__ hout)
{
    __shared__ float h_s[16][NPAD];       // tf32-rounded h (A operand)
    __shared__ float gates_s[16][GPAD];   // recurrent-term accumulators

    const int tid  = threadIdx.x;
    const int wid  = tid >> 5;
    const int lane = tid & 31;
    const int g    = lane >> 2;
    const int tg   = lane & 3;
    const int b0   = blockIdx.x * 16;

    // Warp n-tile ranges: warps 0-3 own 8 tiles, warps 4-7 own 7 (60 total).
    const int nt0 = (wid < 4) ? wid * 8 : 32 + (wid - 4) * 7;
    const int ntn = (wid < 4) ? 8 : 7;

    // Pointwise cell mapping: cell = tid + 256*i (1920 cells = 16 rows x 120).
    int rr[8], dd[8];
    float c[8];
#pragma unroll
    for (int i = 0; i < 8; i++) {
        int cell = tid + 256 * i;
        rr[i] = cell / DMODEL;
        dd[i] = cell % DMODEL;
        c[i]  = 0.0f;
    }

#pragma unroll 1
    for (int t = 0; t < SEQL; t++) {
        if (t > 0) {
            float acc[8][4];
#pragma unroll
            for (int j = 0; j < 8; j++)
#pragma unroll
                for (int i = 0; i < 4; i++) acc[j][i] = 0.0f;

#pragma unroll 1
            for (int kt = 0; kt < KT_TILES; kt++) {
                const int k0 = kt * 8;
                unsigned a[4];
                a[0] = __float_as_uint(h_s[g    ][k0 + tg    ]);
                a[1] = __float_as_uint(h_s[g + 8][k0 + tg    ]);
                a[2] = __float_as_uint(h_s[g    ][k0 + tg + 4]);
                a[3] = __float_as_uint(h_s[g + 8][k0 + tg + 4]);
                const float* bp = Wpk + ((size_t)(nt0 * KT_TILES + kt)) * 64
                                + lane * 2;
#pragma unroll
                for (int j = 0; j < 8; j++) {
                    if (j < ntn) {
                        float2 bv = *(const float2*)(bp + (size_t)j * KT_TILES * 64);
                        mma_tf32(acc[j], a, (const unsigned*)&bv);
                    }
                }
            }
            // Store recurrent terms to gates smem.
#pragma unroll
            for (int j = 0; j < 8; j++) {
                if (j < ntn) {
                    int col = (nt0 + j) * 8 + 2 * tg;
                    *(float2*)&gates_s[g    ][col] = make_float2(acc[j][0], acc[j][1]);
                    *(float2*)&gates_s[g + 8][col] = make_float2(acc[j][2], acc[j][3]);
                }
            }
        }
        __syncthreads();   // gates visible; h_s reads done before overwrite

        // Pointwise LSTM cell update (gate order i, f, g, o); xg exact fp32.
#pragma unroll
        for (int i = 0; i < 8; i++) {
            int cell = tid + 256 * i;
            if (cell < 16 * DMODEL) {
                const int r = rr[i], d = dd[i];
                size_t xb = ((size_t)(b0 + r) * SEQL + t) * H4;
                float gi = xg[xb +            d];
                float gf = xg[xb + DMODEL   + d];
                float gg = xg[xb + 2*DMODEL + d];
                float go = xg[xb + 3*DMODEL + d];
                if (t > 0) {
                    gi += gates_s[r][d];
                    gf += gates_s[r][DMODEL   + d];
                    gg += gates_s[r][2*DMODEL + d];
                    go += gates_s[r][3*DMODEL + d];
                }
                float cn = sig_acc(gf) * c[i] + sig_acc(gi) * tanh_acc(gg);
                c[i] = cn;
                float h = sig_acc(go) * tanh_acc(cn);
                hout[((size_t)(b0 + r) * SEQL + t) * DMODEL + d] = h;
                h_s[r][d] = tf32r(h);       // tf32 operand for next step's mma
            }
        }
        __syncthreads();
    }
}

// ---------------------------------------------------------------------------
// Tensor-core GEMM: C[M,N] = A[M,120] @ W[N,120]^T (+ b1 + b2), tf32 mma,
// fp32 accumulate. A row m optionally gathered: A_row = Emb[idx[m]].
// Block tile 128x128, 256 threads = 8 warps (4 m-warps x 2 n-warps).
// ---------------------------------------------------------------------------
template<bool GATHER>
__global__ __launch_bounds__(256, 2)
void gemm_tc(const float* __restrict__ A,
             const int*   __restrict__ idx,
             const float* __restrict__ Emb,
             const float* __restrict__ W,
             const float* __restrict__ b1,
             const float* __restrict__ b2,
             float* __restrict__ C, int N)
{
    __shared__ float As[128][44];
    __shared__ float Ws[128][44];

    const int tid  = threadIdx.x;
    const int wid  = tid >> 5;
    const int lane = tid & 31;
    const int g    = lane >> 2;
    const int tg   = lane & 3;
    const int m0   = blockIdx.x * 128;
    const int n0   = blockIdx.y * 128;
    const int wm   = wid >> 1;
    const int wn   = wid & 1;

    float acc[2][8][4];
#pragma unroll
    for (int mf = 0; mf < 2; mf++)
#pragma unroll
        for (int nf = 0; nf < 8; nf++)
#pragma unroll
            for (int i = 0; i < 4; i++) acc[mf][nf][i] = 0.0f;

#pragma unroll 1
    for (int kt = 0; kt < 3; kt++) {
        const int k0g = kt * 40;
#pragma unroll
        for (int i = 0; i < 5; i++) {
            int flat = tid + i * 256;
            int row = flat / 10, c4 = flat % 10;
            const float* src;
            if (GATHER)
                src = Emb + (size_t)idx[m0 + row] * DMODEL + k0g + c4 * 4;
            else
                src = A + (size_t)(m0 + row) * DMODEL + k0g + c4 * 4;
            float4 v = *(const float4*)src;
            As[row][c4*4+0] = tf32r(v.x);
            As[row][c4*4+1] = tf32r(v.y);
            As[row][c4*4+2] = tf32r(v.z);
            As[row][c4*4+3] = tf32r(v.w);
        }
#pragma unroll
        for (int i = 0; i < 5; i++) {
            int flat = tid + i * 256;
            int row = flat / 10, c4 = flat % 10;
            float4 v = make_float4(0.f, 0.f, 0.f, 0.f);
            if (n0 + row < N)
                v = *(const float4*)(W + (size_t)(n0 + row) * DMODEL + k0g + c4 * 4);
            Ws[row][c4*4+0] = tf32r(v.x);
            Ws[row][c4*4+1] = tf32r(v.y);
            Ws[row][c4*4+2] = tf32r(v.z);
            Ws[row][c4*4+3] = tf32r(v.w);
        }
        __syncthreads();

#pragma unroll
        for (int kk = 0; kk < 5; kk++) {
            const int k0 = kk * 8;
            unsigned a[2][4];
#pragma unroll
            for (int mf = 0; mf < 2; mf++) {
                int m = wm * 32 + mf * 16 + g;
                a[mf][0] = __float_as_uint(As[m    ][k0 + tg    ]);
                a[mf][1] = __float_as_uint(As[m + 8][k0 + tg    ]);
                a[mf][2] = __float_as_uint(As[m    ][k0 + tg + 4]);
                a[mf][3] = __float_as_uint(As[m + 8][k0 + tg + 4]);
            }
#pragma unroll
            for (int nf = 0; nf < 8; nf++) {
                unsigned b[2];
                int n = wn * 64 + nf * 8 + g;
                b[0] = __float_as_uint(Ws[n][k0 + tg    ]);
                b[1] = __float_as_uint(Ws[n][k0 + tg + 4]);
                mma_tf32(acc[0][nf], a[0], b);
                mma_tf32(acc[1][nf], a[1], b);
            }
        }
        __syncthreads();
    }

#pragma unroll
    for (int mf = 0; mf < 2; mf++) {
        const int m = m0 + wm * 32 + mf * 16 + g;
#pragma unroll
        for (int nf = 0; nf < 8; nf++) {
            const int n = n0 + wn * 64 + nf * 8 + 2 * tg;
            float bs0 = 0.0f, bs1 = 0.0f;
            if (n < N)     { if (b1) bs0 += b1[n];     if (b2) bs0 += b2[n]; }
            if (n + 1 < N) { if (b1) bs1 += b1[n + 1]; if (b2) bs1 += b2[n + 1]; }
            float* r0 = C + (size_t)m * N;
            float* r1 = C + (size_t)(m + 8) * N;
            if (n < N) {
                r0[n] = acc[mf][nf][0] + bs0;
                r1[n] = acc[mf][nf][2] + bs0;
            }
            if (n + 1 < N) {
                r0[n + 1] = acc[mf][nf][1] + bs1;
                r1[n + 1] = acc[mf][nf][3] + bs1;
            }
        }
    }
}

// ---------------------------------------------------------------------------
// LayerNorm over D=120: one warp per row (exact fp32).
// ---------------------------------------------------------------------------
__global__ __launch_bounds__(256)
void ln_k(const float* __restrict__ in,
          const float* __restrict__ gamma,
          const float* __restrict__ beta,
          float* __restrict__ out)
{
    const int row  = blockIdx.x * 8 + (threadIdx.x >> 5);
    const int lane = threadIdx.x & 31;
    const float* rp = in + (size_t)row * DMODEL;

    float v[4];
    float s = 0.0f, s2 = 0.0f;
#pragma unroll
    for (int i = 0; i < 4; i++) {
        int d = lane + 32 * i;
        v[i] = (d < DMODEL) ? rp[d] : 0.0f;
        s  += v[i];
        s2 += v[i] * v[i];
    }
#pragma unroll
    for (int off = 16; off > 0; off >>= 1) {
        s  += __shfl_xor_sync(0xffffffffu, s,  off);
        s2 += __shfl_xor_sync(0xffffffffu, s2, off);
    }
    const float mu   = s  * (1.0f / DMODEL);
    const float var  = s2 * (1.0f / DMODEL) - mu * mu;
    const float rstd = rsqrtf(var + 1e-5f);

    float* op = out + (size_t)row * DMODEL;
#pragma unroll
    for (int i = 0; i < 4; i++) {
        int d = lane + 32 * i;
        if (d < DMODEL)
            op[d] = (v[i] - mu) * rstd * gamma[d] + beta[d];
    }
}

// ---------------------------------------------------------------------------
extern "C" void kernel_launch(void* const* d_in, const int* in_sizes, int n_in,
                              void* d_out, int out_size)
{
    const int*   x     = (const int*)  d_in[0];
    const float* embed = (const float*)d_in[1];
    const float* Wih0  = (const float*)d_in[2];
    const float* Whh0  = (const float*)d_in[3];
    const float* bih0  = (const float*)d_in[4];
    const float* bhh0  = (const float*)d_in[5];
    const float* Wih1  = (const float*)d_in[6];
    const float* Whh1  = (const float*)d_in[7];
    const float* bih1  = (const float*)d_in[8];
    const float* bhh1  = (const float*)d_in[9];
    const float* gamma = (const float*)d_in[10];
    const float* beta  = (const float*)d_in[11];
    float* out = (float*)d_out;

    float *xg, *h, *ln, *wpk;
    cudaGetSymbolAddress((void**)&xg,  g_xg);
    cudaGetSymbolAddress((void**)&h,   g_h);
    cudaGetSymbolAddress((void**)&ln,  g_ln);
    cudaGetSymbolAddress((void**)&wpk, g_wpk);

    dim3 g480(MTOK / 128, (H4 + 127) / 128);     // (512, 4)
    dim3 g433(MTOK / 128, (VOCAB + 127) / 128);  // (512, 4)
    const int packGrid = (NT_TILES * KT_TILES * 32 + 255) / 256;

    // Pack Whh0/Whh1 into B-fragment layout (tiny, overlaps with gemm queue).
    pack_whh<<<packGrid, 256>>>(Whh0, wpk);
    pack_whh<<<packGrid, 256>>>(Whh1, wpk + WPK_ELEMS);

    // Layer 0: xg0 = embed[x] @ Wih0^T + bih0 + bhh0 (gather fused, tf32 TC)
    gemm_tc<true ><<<g480, 256>>>(nullptr, x, embed, Wih0, bih0, bhh0, xg, H4);
    // LSTM layer 0 recurrence (tf32 tensor-core)
    lstm_tc<<<BATCH / 16, 256>>>(xg, wpk, h);
    // Layer 1: xg1 = h0 @ Wih1^T + bih1 + bhh1 (tf32 TC)
    gemm_tc<false><<<g480, 256>>>(h, nullptr, nullptr, Wih1, bih1, bhh1, xg, H4);
    // LSTM layer 1 recurrence (reuse h buffer)
    lstm_tc<<<BATCH / 16, 256>>>(xg, wpk + WPK_ELEMS, h);
    // LayerNorm
    ln_k<<<MTOK / 8, 256>>>(h, gamma, beta, ln);
    // Tied-embedding head: logits = ln @ embed^T (tf32 TC)
    gemm_tc<false><<<g433, 256>>>(ln, nullptr, nullptr, embed, nullptr, nullptr,
                                  out, VOCAB);
}

// round 10
// speedup vs baseline: 2.1894x; 1.1906x over previous
#include <cuda_runtime.h>
#include <math.h>

#define VOCAB 433
#define DMODEL 120
#define BATCH 4096
#define SEQL 16
#define H4 480
#define MTOK (BATCH*SEQL)   // 65536

#define NT_TILES 60          // 480/8 n-tiles (permuted: nt = db*4 + gate)
#define KT_TILES 15          // 120/8 k-tiles
#define WMAT (NT_TILES*KT_TILES*64)   // 57600 floats per packed matrix

// Scratch (static __device__ arrays: allocation-free per harness rules)
__device__ float g_h0[(size_t)MTOK * DMODEL]; // 31.5 MB
__device__ float g_h1[(size_t)MTOK * DMODEL]; // 31.5 MB
__device__ float g_ln[(size_t)MTOK * DMODEL]; // 31.5 MB
__device__ float g_wpk[2][2 * WMAT];          // [layer][Wih | Whh] packed tf32

// Accurate activations (ex2-based; 2^-22.5 max err even under fast-math).
#define LOG2E 1.4426950408889634f
__device__ __forceinline__ float sig_acc(float x) {
    return 1.0f / (1.0f + exp2f(-x * LOG2E));
}
__device__ __forceinline__ float tanh_acc(float x) {
    float e = exp2f(x * (2.0f * LOG2E));
    return 1.0f - 2.0f / (e + 1.0f);
}

__device__ __forceinline__ float tf32r(float x) {
    float r;
    asm("cvt.rna.tf32.f32 %0, %1;" : "=f"(r) : "f"(x));
    return r;
}

// m16n8k8 tf32 tensor-core mma, fp32 accumulate.
__device__ __forceinline__ void mma_tf32(float* d, const unsigned* a,
                                         const unsigned* b) {
    asm volatile(
        "mma.sync.aligned.m16n8k8.row.col.f32.tf32.tf32.f32 "
        "{%0,%1,%2,%3}, {%4,%5,%6,%7}, {%8,%9}, {%0,%1,%2,%3};\n"
        : "+f"(d[0]), "+f"(d[1]), "+f"(d[2]), "+f"(d[3])
        : "r"(a[0]), "r"(a[1]), "r"(a[2]), "r"(a[3]), "r"(b[0]), "r"(b[1]));
}

// ---------------------------------------------------------------------------
// Pack W[480,120] into gate-permuted per-(n8,k8)-tile B-fragment layout:
// tile nt = db*4 + q (db = d-block 0..14, q = gate 0..3); tile row g maps to
// original W row q*120 + db*8 + g. Frag: lane(g,tg) -> W[row][kt*8+tg], +4.
// ---------------------------------------------------------------------------
__global__ void pack_w(const float* __restrict__ W, float* __restrict__ Wpk)
{
    int idx = blockIdx.x * 256 + threadIdx.x;     // 0..28799
    if (idx >= NT_TILES * KT_TILES * 32) return;
    int lane = idx & 31, tile = idx >> 5;
    int kt = tile % KT_TILES, nt = tile / KT_TILES;
    int db = nt >> 2, q = nt & 3;
    int g = lane >> 2, tg = lane & 3;
    int row = q * DMODEL + db * 8 + g;
    int k = kt * 8 + tg;
    Wpk[tile * 64 + lane * 2 + 0] = tf32r(W[row * DMODEL + k]);
    Wpk[tile * 64 + lane * 2 + 1] = tf32r(W[row * DMODEL + k + 4]);
}

// ---------------------------------------------------------------------------
// Fused LSTM layer: input GEMM + recurrence + cell update in one kernel.
// Block = 16 batch rows x 16 timesteps, 256 threads / 8 warps.
// Per step: gates[16,480] = x(t)@Wih^T + h(t-1)@Whh^T via m16n8k8 tf32 mma.
// Gate-permuted packing => warp w owns d-blocks {2w,2w+1} (warp 7: {14}),
// holding i,f,g,o for its cells in its own acc regs => register-local
// pointwise, ONE barrier per step (h_s/x_s ping-pong).
// ---------------------------------------------------------------------------
template<bool GATHER>
__global__ __launch_bounds__(256)
void lstm_fused(const float* __restrict__ xin,   // layer1: h0 [B,L,D]
                const int*   __restrict__ xtok,  // layer0: tokens [B,L]
                const float* __restrict__ embed,
                const float* __restrict__ wpk,   // [Wih | Whh] packed
                const float* __restrict__ bih,
                const float* __restrict__ bhh,
                float* __restrict__ hout)
{
    __shared__ float x_s[2][16][124];
    __shared__ float h_s[2][16][124];
    __shared__ int   idx_s[256];

    const int tid  = threadIdx.x;
    const int wid  = tid >> 5;
    const int lane = tid & 31;
    const int g    = lane >> 2;
    const int tg   = lane & 3;
    const int b0   = blockIdx.x * 16;

    // Ownership: warp w<7 owns d-blocks {2w, 2w+1} (8 tiles); warp 7 owns {14}.
    const int dbn = (wid < 7) ? 2 : 1;
    const int db0 = 2 * wid;
    const int nt0 = db0 * 4;
    const int ntn = dbn * 4;

    // Bias regs: bias[jdb][gate][col]
    float bias[2][4][2];
#pragma unroll
    for (int jdb = 0; jdb < 2; jdb++) {
        if (jdb < dbn) {
#pragma unroll
            for (int q = 0; q < 4; q++)
#pragma unroll
                for (int c2 = 0; c2 < 2; c2++) {
                    int d = (db0 + jdb) * 8 + 2 * tg + c2;
                    int row = q * DMODEL + d;
                    bias[jdb][q][c2] = bih[row] + bhh[row];
                }
        }
    }

    // Token indices for this block (GATHER only).
    if (GATHER)
        idx_s[tid] = xtok[(size_t)(b0 + (tid >> 4)) * SEQL + (tid & 15)];
    __syncthreads();

    // Load x(0) into x_s[0] (tf32-rounded).
#pragma unroll
    for (int i = 0; i < 2; i++) {
        int flat = tid + 256 * i;
        if (flat < 480) {
            int row = flat / 30, c4 = flat % 30;
            const float* src = GATHER
                ? embed + (size_t)idx_s[row * 16] * DMODEL + c4 * 4
                : xin + ((size_t)(b0 + row) * SEQL) * DMODEL + c4 * 4;
            float4 v = *(const float4*)src;
            *(float4*)&x_s[0][row][c4 * 4] = make_float4(
                tf32r(v.x), tf32r(v.y), tf32r(v.z), tf32r(v.w));
        }
    }
    __syncthreads();

    float c[8];
#pragma unroll
    for (int i = 0; i < 8; i++) c[i] = 0.0f;

#pragma unroll 1
    for (int t = 0; t < SEQL; t++) {
        const int cur = t & 1, nxt = cur ^ 1;
        float (*xc)[124] = x_s[cur];
        float (*hc)[124] = h_s[cur];

        // Prefetch x(t+1) early (LDG latency overlaps the mma phase).
        float4 px[2];
        if (t < 15) {
#pragma unroll
            for (int i = 0; i < 2; i++) {
                int flat = tid + 256 * i;
                if (flat < 480) {
                    int row = flat / 30, c4 = flat % 30;
                    const float* src = GATHER
                        ? embed + (size_t)idx_s[row * 16 + t + 1] * DMODEL + c4 * 4
                        : xin + ((size_t)(b0 + row) * SEQL + t + 1) * DMODEL + c4 * 4;
                    px[i] = *(const float4*)src;
                }
            }
        }

        float acc[8][4];
#pragma unroll
        for (int j = 0; j < 8; j++)
#pragma unroll
            for (int v = 0; v < 4; v++) acc[j][v] = 0.0f;

        // Input-weight part: x(t) @ Wih^T
#pragma unroll 3
        for (int kt = 0; kt < KT_TILES; kt++) {
            const int k0 = kt * 8;
            unsigned a[4];
            a[0] = __float_as_uint(xc[g    ][k0 + tg    ]);
            a[1] = __float_as_uint(xc[g + 8][k0 + tg    ]);
            a[2] = __float_as_uint(xc[g    ][k0 + tg + 4]);
            a[3] = __float_as_uint(xc[g + 8][k0 + tg + 4]);
            const float* bp = wpk + ((size_t)(nt0 * KT_TILES + kt)) * 64 + lane * 2;
#pragma unroll
            for (int j = 0; j < 8; j++) {
                if (j < ntn) {
                    float2 bv = *(const float2*)(bp + j * (KT_TILES * 64));
                    mma_tf32(acc[j], a, (const unsigned*)&bv);
                }
            }
        }
        // Recurrent part: h(t-1) @ Whh^T
        if (t > 0) {
            const float* whh = wpk + WMAT;
#pragma unroll 3
            for (int kt = 0; kt < KT_TILES; kt++) {
                const int k0 = kt * 8;
                unsigned a[4];
                a[0] = __float_as_uint(hc[g    ][k0 + tg    ]);
                a[1] = __float_as_uint(hc[g + 8][k0 + tg    ]);
                a[2] = __float_as_uint(hc[g    ][k0 + tg + 4]);
                a[3] = __float_as_uint(hc[g + 8][k0 + tg + 4]);
                const float* bp = whh + ((size_t)(nt0 * KT_TILES + kt)) * 64 + lane * 2;
#pragma unroll
                for (int j = 0; j < 8; j++) {
                    if (j < ntn) {
                        float2 bv = *(const float2*)(bp + j * (KT_TILES * 64));
                        mma_tf32(acc[j], a, (const unsigned*)&bv);
                    }
                }
            }
        }

        // Register-local pointwise cell update (gates i,f,g,o in own regs).
#pragma unroll
        for (int jdb = 0; jdb < 2; jdb++) {
            if (jdb < dbn) {
                const int j0 = jdb * 4;
#pragma unroll
                for (int rs = 0; rs < 2; rs++) {
                    float h2[2];
#pragma unroll
                    for (int cs = 0; cs < 2; cs++) {
                        const int v = rs * 2 + cs;
                        float gi = acc[j0 + 0][v] + bias[jdb][0][cs];
                        float gf = acc[j0 + 1][v] + bias[jdb][1][cs];
                        float gg = acc[j0 + 2][v] + bias[jdb][2][cs];
                        float go = acc[j0 + 3][v] + bias[jdb][3][cs];
                        const int ci = jdb * 4 + rs * 2 + cs;
                        float cn = sig_acc(gf) * c[ci] + sig_acc(gi) * tanh_acc(gg);
                        c[ci] = cn;
                        h2[cs] = sig_acc(go) * tanh_acc(cn);
                    }
                    const int r = g + rs * 8;
                    const int d = (db0 + jdb) * 8 + 2 * tg;
                    *(float2*)&hout[((size_t)(b0 + r) * SEQL + t) * DMODEL + d] =
                        make_float2(h2[0], h2[1]);
                    h_s[nxt][r][d]     = tf32r(h2[0]);
                    h_s[nxt][r][d + 1] = tf32r(h2[1]);
                }
            }
        }

        // Stage prefetched x(t+1).
        if (t < 15) {
#pragma unroll
            for (int i = 0; i < 2; i++) {
                int flat = tid + 256 * i;
                if (flat < 480) {
                    int row = flat / 30, c4 = flat % 30;
                    *(float4*)&x_s[nxt][row][c4 * 4] = make_float4(
                        tf32r(px[i].x), tf32r(px[i].y),
                        tf32r(px[i].z), tf32r(px[i].w));
                }
            }
        }
        __syncthreads();
    }
}

// ---------------------------------------------------------------------------
// Tensor-core GEMM (logits): C[M,N] = A[M,120] @ W[N,120]^T, tf32 mma.
// Block tile 128x128, 256 threads = 8 warps. (unchanged, known-good)
// ---------------------------------------------------------------------------
__global__ __launch_bounds__(256, 2)
void gemm_tc(const float* __restrict__ A,
             const float* __restrict__ W,
             float* __restrict__ C, int N)
{
    __shared__ float As[128][44];
    __shared__ float Ws[128][44];

    const int tid  = threadIdx.x;
    const int wid  = tid >> 5;
    const int lane = tid & 31;
    const int g    = lane >> 2;
    const int tg   = lane & 3;
    const int m0   = blockIdx.x * 128;
    const int n0   = blockIdx.y * 128;
    const int wm   = wid >> 1;
    const int wn   = wid & 1;

    float acc[2][8][4];
#pragma unroll
    for (int mf = 0; mf < 2; mf++)
#pragma unroll
        for (int nf = 0; nf < 8; nf++)
#pragma unroll
            for (int i = 0; i < 4; i++) acc[mf][nf][i] = 0.0f;

#pragma unroll 1
    for (int kt = 0; kt < 3; kt++) {
        const int k0g = kt * 40;
#pragma unroll
        for (int i = 0; i < 5; i++) {
            int flat = tid + i * 256;
            int row = flat / 10, c4 = flat % 10;
            float4 v = *(const float4*)(A + (size_t)(m0 + row) * DMODEL + k0g + c4 * 4);
            As[row][c4*4+0] = tf32r(v.x);
            As[row][c4*4+1] = tf32r(v.y);
            As[row][c4*4+2] = tf32r(v.z);
            As[row][c4*4+3] = tf32r(v.w);
        }
#pragma unroll
        for (int i = 0; i < 5; i++) {
            int flat = tid + i * 256;
            int row = flat / 10, c4 = flat % 10;
            float4 v = make_float4(0.f, 0.f, 0.f, 0.f);
            if (n0 + row < N)
                v = *(const float4*)(W + (size_t)(n0 + row) * DMODEL + k0g + c4 * 4);
            Ws[row][c4*4+0] = tf32r(v.x);
            Ws[row][c4*4+1] = tf32r(v.y);
            Ws[row][c4*4+2] = tf32r(v.z);
            Ws[row][c4*4+3] = tf32r(v.w);
        }
        __syncthreads();

#pragma unroll
        for (int kk = 0; kk < 5; kk++) {
            const int k0 = kk * 8;
            unsigned a[2][4];
#pragma unroll
            for (int mf = 0; mf < 2; mf++) {
                int m = wm * 32 + mf * 16 + g;
                a[mf][0] = __float_as_uint(As[m    ][k0 + tg    ]);
                a[mf][1] = __float_as_uint(As[m + 8][k0 + tg    ]);
                a[mf][2] = __float_as_uint(As[m    ][k0 + tg + 4]);
                a[mf][3] = __float_as_uint(As[m + 8][k0 + tg + 4]);
            }
#pragma unroll
            for (int nf = 0; nf < 8; nf++) {
                unsigned b[2];
                int n = wn * 64 + nf * 8 + g;
                b[0] = __float_as_uint(Ws[n][k0 + tg    ]);
                b[1] = __float_as_uint(Ws[n][k0 + tg + 4]);
                mma_tf32(acc[0][nf], a[0], b);
                mma_tf32(acc[1][nf], a[1], b);
            }
        }
        __syncthreads();
    }

#pragma unroll
    for (int mf = 0; mf < 2; mf++) {
        const int m = m0 + wm * 32 + mf * 16 + g;
#pragma unroll
        for (int nf = 0; nf < 8; nf++) {
            const int n = n0 + wn * 64 + nf * 8 + 2 * tg;
            float* r0 = C + (size_t)m * N;
            float* r1 = C + (size_t)(m + 8) * N;
            if (n < N) {
                r0[n] = acc[mf][nf][0];
                r1[n] = acc[mf][nf][2];
            }
            if (n + 1 < N) {
                r0[n + 1] = acc[mf][nf][1];
                r1[n + 1] = acc[mf][nf][3];
            }
        }
    }
}

// ---------------------------------------------------------------------------
// LayerNorm over D=120: one warp per row (exact fp32).
// ---------------------------------------------------------------------------
__global__ __launch_bounds__(256)
void ln_k(const float* __restrict__ in,
          const float* __restrict__ gamma,
          const float* __restrict__ beta,
          float* __restrict__ out)
{
    const int row  = blockIdx.x * 8 + (threadIdx.x >> 5);
    const int lane = threadIdx.x & 31;
    const float* rp = in + (size_t)row * DMODEL;

    float v[4];
    float s = 0.0f, s2 = 0.0f;
#pragma unroll
    for (int i = 0; i < 4; i++) {
        int d = lane + 32 * i;
        v[i] = (d < DMODEL) ? rp[d] : 0.0f;
        s  += v[i];
        s2 += v[i] * v[i];
    }
#pragma unroll
    for (int off = 16; off > 0; off >>= 1) {
        s  += __shfl_xor_sync(0xffffffffu, s,  off);
        s2 += __shfl_xor_sync(0xffffffffu, s2, off);
    }
    const float mu   = s  * (1.0f / DMODEL);
    const float var  = s2 * (1.0f / DMODEL) - mu * mu;
    const float rstd = rsqrtf(var + 1e-5f);

    float* op = out + (size_t)row * DMODEL;
#pragma unroll
    for (int i = 0; i < 4; i++) {
        int d = lane + 32 * i;
        if (d < DMODEL)
            op[d] = (v[i] - mu) * rstd * gamma[d] + beta[d];
    }
}

// ---------------------------------------------------------------------------
extern "C" void kernel_launch(void* const* d_in, const int* in_sizes, int n_in,
                              void* d_out, int out_size)
{
    const int*   x     = (const int*)  d_in[0];
    const float* embed = (const float*)d_in[1];
    const float* Wih0  = (const float*)d_in[2];
    const float* Whh0  = (const float*)d_in[3];
    const float* bih0  = (const float*)d_in[4];
    const float* bhh0  = (const float*)d_in[5];
    const float* Wih1  = (const float*)d_in[6];
    const float* Whh1  = (const float*)d_in[7];
    const float* bih1  = (const float*)d_in[8];
    const float* bhh1  = (const float*)d_in[9];
    const float* gamma = (const float*)d_in[10];
    const float* beta  = (const float*)d_in[11];
    float* out = (float*)d_out;

    float *h0, *h1, *ln, *wpk;
    cudaGetSymbolAddress((void**)&h0,  g_h0);
    cudaGetSymbolAddress((void**)&h1,  g_h1);
    cudaGetSymbolAddress((void**)&ln,  g_ln);
    cudaGetSymbolAddress((void**)&wpk, g_wpk);

    const int packGrid = (NT_TILES * KT_TILES * 32 + 255) / 256;
    dim3 g433(MTOK / 128, (VOCAB + 127) / 128);  // (512, 4)

    // Pack all four weight matrices (gate-permuted fragment layout).
    pack_w<<<packGrid, 256>>>(Wih0, wpk);
    pack_w<<<packGrid, 256>>>(Whh0, wpk + WMAT);
    pack_w<<<packGrid, 256>>>(Wih1, wpk + 2 * WMAT);
    pack_w<<<packGrid, 256>>>(Whh1, wpk + 3 * WMAT);

    // Layer 0: fused embed-gather + input GEMM + recurrence.
    lstm_fused<true ><<<BATCH / 16, 256>>>(nullptr, x, embed, wpk,
                                           bih0, bhh0, h0);
    // Layer 1: fused (input = h0).
    lstm_fused<false><<<BATCH / 16, 256>>>(h0, nullptr, nullptr, wpk + 2 * WMAT,
                                           bih1, bhh1, h1);
    // LayerNorm
    ln_k<<<MTOK / 8, 256>>>(h1, gamma, beta, ln);
    // Tied-embedding head: logits = ln @ embed^T
    gemm_tc<<<g433, 256>>>(ln, embed, out, VOCAB);
}